// round 4
// baseline (speedup 1.0000x reference)
#include <cuda_runtime.h>

#define NN 100000
#define EE 1600000

// ---------------- scratch (no allocations allowed) ----------------
__device__ int   g_is64;
__device__ int   g_deg[NN];
__device__ int   g_off[NN];
__device__ int   g_cur[NN];
__device__ int   g_csr[EE];
__device__ float g_h[NN * 128];
__device__ float g_t[NN * 128];
__device__ float g_x[NN * 128];

__device__ __forceinline__ float* gbuf(int i) {
    return (i == 0) ? g_h : (i == 1) ? g_t : g_x;
}

// ---------------- dtype detection (int64 vs silently-downcast int32) ----------------
// If edge_index is truly int64, all sampled values lie in [0, NN). If the data is
// int32 read as int64, a value combines two node ids -> almost surely out of range.
__global__ void k_detect(const long long* __restrict__ e64) {
    __shared__ int bad;
    if (threadIdx.x == 0) bad = 0;
    __syncthreads();
    for (int i = threadIdx.x; i < 4096; i += blockDim.x) {
        long long v = e64[i];
        if (v < 0 || v >= NN) bad = 1;
    }
    __syncthreads();
    if (threadIdx.x == 0) g_is64 = bad ? 0 : 1;
}

// ---------------- CSR build ----------------
__global__ void k_zero_deg() {
    int i = blockIdx.x * blockDim.x + threadIdx.x;
    if (i < NN) g_deg[i] = 0;
}

__device__ __forceinline__ int edge_at(const void* ei, int idx) {
    if (g_is64) return (int)((const long long*)ei)[idx];
    return ((const int*)ei)[idx];
}

__global__ void k_hist(const void* __restrict__ ei) {
    int e = blockIdx.x * blockDim.x + threadIdx.x;
    if (e < EE) {
        int d = edge_at(ei, EE + e);
        if ((unsigned)d < (unsigned)NN) atomicAdd(&g_deg[d], 1);
    }
}

// single-block exclusive scan over g_deg -> g_off (and g_cur copy)
__global__ void k_scan() {
    __shared__ int smem[1024];
    __shared__ int carry;
    if (threadIdx.x == 0) carry = 0;
    __syncthreads();
    for (int base = 0; base < NN; base += 1024) {
        int i = base + threadIdx.x;
        int v = (i < NN) ? g_deg[i] : 0;
        smem[threadIdx.x] = v;
        __syncthreads();
        #pragma unroll
        for (int off = 1; off < 1024; off <<= 1) {
            int t = 0;
            if ((int)threadIdx.x >= off) t = smem[threadIdx.x - off];
            __syncthreads();
            smem[threadIdx.x] += t;
            __syncthreads();
        }
        int incl = smem[threadIdx.x];
        int excl = incl - v;
        if (i < NN) {
            g_off[i] = carry + excl;
            g_cur[i] = carry + excl;
        }
        __syncthreads();
        if (threadIdx.x == 0) carry += smem[1023];
        __syncthreads();
    }
}

__global__ void k_fill(const void* __restrict__ ei) {
    int e = blockIdx.x * blockDim.x + threadIdx.x;
    if (e < EE) {
        int d = edge_at(ei, EE + e);
        int s = edge_at(ei, e);
        if ((unsigned)d < (unsigned)NN && (unsigned)s < (unsigned)NN) {
            int p = atomicAdd(&g_cur[d], 1);
            if ((unsigned)p < (unsigned)EE) g_csr[p] = s;
        }
    }
}

// ---------------- aggregation: h = (1+eps)*x + sum_{j in N(i)} x_j ----------------
// warp per node; F = 64 (float2/lane) or 128 (float4/lane)
// SRC == -1: read from xin parameter, else from gbuf(SRC). DST: gbuf(DST).
template <int F, int SRC, int DST>
__global__ void k_agg(const float* __restrict__ xin,
                      const float* __restrict__ epsp) {
    int gw = (blockIdx.x * blockDim.x + threadIdx.x) >> 5;
    if (gw >= NN) return;
    int lane = threadIdx.x & 31;
    const float* src = (SRC < 0) ? xin : gbuf(SRC);
    float* h = gbuf(DST);
    float scale = 1.0f + __ldg(epsp);
    // clamp bounds defensively so no CSR state can produce unbounded loops
    int start = g_off[gw];
    int end = g_cur[gw];   // off + deg (valid edges only)
    if (start < 0) start = 0;
    if (end > EE) end = EE;
    if (end < start) end = start;

    if (F == 128) {
        const float4* x4 = (const float4*)src;
        float4 a = x4[gw * 32 + lane];
        float4 acc = make_float4(a.x * scale, a.y * scale, a.z * scale, a.w * scale);
        for (int j = start; j < end; j++) {
            int s = g_csr[j];
            float4 v = x4[s * 32 + lane];
            acc.x += v.x; acc.y += v.y; acc.z += v.z; acc.w += v.w;
        }
        ((float4*)h)[gw * 32 + lane] = acc;
    } else {
        const float2* x2 = (const float2*)src;
        float2 a = x2[gw * 32 + lane];
        float2 acc = make_float2(a.x * scale, a.y * scale);
        for (int j = start; j < end; j++) {
            int s = g_csr[j];
            float2 v = x2[s * 32 + lane];
            acc.x += v.x; acc.y += v.y;
        }
        ((float2*)h)[gw * 32 + lane] = acc;
    }
}

// ---------------- SGEMM: gbuf(DST) = relu(gbuf(SRC) @ W + b) ----------------
// BM=64, BN=64, BK=16, 256 threads, 4x4 outputs per thread
template <int K, int HOUT, bool RELU, int SRC, int DST>
__global__ __launch_bounds__(256) void k_gemm(const float* __restrict__ W,
                                              const float* __restrict__ B) {
    const int BM = 64, BN = 64, BK = 16;
    __shared__ __align__(16) float As[BK][BM];
    __shared__ __align__(16) float Bs[BK][BN];

    const float* X = gbuf(SRC);
    float* Y = gbuf(DST);

    int tid = threadIdx.x;
    int row0 = blockIdx.y * BM;
    int col0 = blockIdx.x * BN;
    int tx = tid & 15;     // 0..15 -> 4 cols each
    int ty = tid >> 4;     // 0..15 -> 4 rows each

    int ar = tid >> 2;     // 0..63  (A row within tile)
    int akv = tid & 3;     // 0..3   (A float4 within BK)
    int br = tid >> 4;     // 0..15  (B row within BK)
    int bnv = tid & 15;    // 0..15  (B float4 within BN)

    float acc[4][4] = {};

    for (int k0 = 0; k0 < K; k0 += BK) {
        float4 av = make_float4(0.f, 0.f, 0.f, 0.f);
        int arow = row0 + ar;
        if (arow < NN) av = *(const float4*)&X[arow * K + k0 + akv * 4];
        As[akv * 4 + 0][ar] = av.x;
        As[akv * 4 + 1][ar] = av.y;
        As[akv * 4 + 2][ar] = av.z;
        As[akv * 4 + 3][ar] = av.w;

        float4 bv = *(const float4*)&W[(k0 + br) * HOUT + col0 + bnv * 4];
        *(float4*)&Bs[br][bnv * 4] = bv;

        __syncthreads();
        #pragma unroll
        for (int kk = 0; kk < BK; kk++) {
            float4 a4 = *(float4*)&As[kk][ty * 4];
            float4 b4 = *(float4*)&Bs[kk][tx * 4];
            float a[4] = {a4.x, a4.y, a4.z, a4.w};
            float b[4] = {b4.x, b4.y, b4.z, b4.w};
            #pragma unroll
            for (int i = 0; i < 4; i++)
                #pragma unroll
                for (int j = 0; j < 4; j++)
                    acc[i][j] += a[i] * b[j];
        }
        __syncthreads();
    }

    #pragma unroll
    for (int i = 0; i < 4; i++) {
        int r = row0 + ty * 4 + i;
        if (r < NN) {
            #pragma unroll
            for (int j = 0; j < 4; j++) {
                int c = col0 + tx * 4 + j;
                float v = acc[i][j] + B[c];
                if (RELU) v = fmaxf(v, 0.0f);
                Y[r * HOUT + c] = v;
            }
        }
    }
}

// ---------------- final FC (N,64)@(64,8)+b and emb copy ----------------
template <int SRC>
__global__ void k_fc(const float* __restrict__ W,
                     const float* __restrict__ B,
                     float* __restrict__ out,
                     float* __restrict__ emb) {
    int gw = (blockIdx.x * blockDim.x + threadIdx.x) >> 5;
    if (gw >= NN) return;
    int lane = threadIdx.x & 31;
    const float* X = gbuf(SRC);
    float v0 = X[gw * 64 + lane];
    float v1 = X[gw * 64 + 32 + lane];
    emb[gw * 64 + lane] = v0;
    emb[gw * 64 + 32 + lane] = v1;
    #pragma unroll
    for (int j = 0; j < 8; j++) {
        float p = v0 * W[lane * 8 + j] + v1 * W[(lane + 32) * 8 + j];
        #pragma unroll
        for (int o = 16; o > 0; o >>= 1)
            p += __shfl_down_sync(0xffffffffu, p, o);
        if (lane == 0) out[gw * 8 + j] = p + B[j];
    }
}

// ---------------- launch ----------------
extern "C" void kernel_launch(void* const* d_in, const int* in_sizes, int n_in,
                              void* d_out, int out_size) {
    const float* x    = (const float*)d_in[0];
    const void*  ei   = d_in[1];                 // int32 or int64, detected on device
    const float* eps1 = (const float*)d_in[2];
    const float* eps2 = (const float*)d_in[3];
    const float* eps3 = (const float*)d_in[4];
    const float* W1a  = (const float*)d_in[5];
    const float* b1a  = (const float*)d_in[6];
    const float* W1b  = (const float*)d_in[7];
    const float* b1b  = (const float*)d_in[8];
    const float* W2a  = (const float*)d_in[9];
    const float* b2a  = (const float*)d_in[10];
    const float* W2b  = (const float*)d_in[11];
    const float* b2b  = (const float*)d_in[12];
    const float* W3a  = (const float*)d_in[13];
    const float* b3a  = (const float*)d_in[14];
    const float* W3b  = (const float*)d_in[15];
    const float* b3b  = (const float*)d_in[16];
    const float* Wfc  = (const float*)d_in[17];
    const float* bfc  = (const float*)d_in[18];

    float* out = (float*)d_out;             // (N, 8)
    float* emb = out + NN * 8;              // (N, 64)

    // CSR build (once per launch; deterministic work)
    k_detect<<<1, 1024>>>((const long long*)ei);
    k_zero_deg<<<(NN + 255) / 256, 256>>>();
    k_hist<<<(EE + 255) / 256, 256>>>(ei);
    k_scan<<<1, 1024>>>();
    k_fill<<<(EE + 255) / 256, 256>>>(ei);

    const int aggBlocks = (NN * 32 + 255) / 256;
    dim3 g128(2, (NN + 63) / 64);
    dim3 g64(1, (NN + 63) / 64);

    // Buffers: 0 = g_h (agg out), 1 = g_t (mid), 2 = g_x (layer out)
    // Layer 1: F_IN=64 -> 128 -> 128
    k_agg<64, -1, 0><<<aggBlocks, 256>>>(x, eps1);
    k_gemm<64, 128, true, 0, 1><<<g128, 256>>>(W1a, b1a);
    k_gemm<128, 128, true, 1, 2><<<g128, 256>>>(W1b, b1b);

    // Layer 2: 128 -> 128 -> 128
    k_agg<128, 2, 0><<<aggBlocks, 256>>>(nullptr, eps2);
    k_gemm<128, 128, true, 0, 1><<<g128, 256>>>(W2a, b2a);
    k_gemm<128, 128, true, 1, 2><<<g128, 256>>>(W2b, b2b);

    // Layer 3: 128 -> 64 -> 64
    k_agg<128, 2, 0><<<aggBlocks, 256>>>(nullptr, eps3);
    k_gemm<128, 64, true, 0, 1><<<g64, 256>>>(W3a, b3a);
    k_gemm<64, 64, true, 1, 2><<<g64, 256>>>(W3b, b3b);

    // FC + emb
    k_fc<2><<<aggBlocks, 256>>>(Wfc, bfc, out, emb);
}

// round 5
// speedup vs baseline: 1.2713x; 1.2713x over previous
#include <cuda_runtime.h>

#define NN 100000
#define EE 1600000
#define SCAN_BLK 1024
#define SCAN_NB ((NN + SCAN_BLK - 1) / SCAN_BLK)   // 98

// ---------------- scratch (no allocations allowed) ----------------
__device__ int   g_is64;
__device__ int   g_deg[NN];
__device__ int   g_off[NN];
__device__ int   g_cur[NN];
__device__ int   g_csr[EE];
__device__ int   g_part[128];
__device__ int   g_partoff[128];
__device__ float g_h[NN * 128];
__device__ float g_t[NN * 128];
__device__ float g_x[NN * 128];

__device__ __forceinline__ float* gbuf(int i) {
    return (i == 0) ? g_h : (i == 1) ? g_t : g_x;
}

// ---------------- dtype detection (int64 vs silently-downcast int32) ----------------
__global__ void k_detect(const long long* __restrict__ e64) {
    __shared__ int bad;
    if (threadIdx.x == 0) bad = 0;
    __syncthreads();
    for (int i = threadIdx.x; i < 4096; i += blockDim.x) {
        long long v = e64[i];
        if (v < 0 || v >= NN) bad = 1;
    }
    __syncthreads();
    if (threadIdx.x == 0) g_is64 = bad ? 0 : 1;
}

// ---------------- CSR build ----------------
__global__ void k_zero_deg() {
    int i = blockIdx.x * blockDim.x + threadIdx.x;
    if (i < NN) g_deg[i] = 0;
}

__device__ __forceinline__ int edge_at(const void* ei, int idx) {
    if (g_is64) return (int)((const long long*)ei)[idx];
    return ((const int*)ei)[idx];
}

__global__ void k_hist(const void* __restrict__ ei) {
    int e = blockIdx.x * blockDim.x + threadIdx.x;
    if (e < EE) {
        int d = edge_at(ei, EE + e);
        if ((unsigned)d < (unsigned)NN) atomicAdd(&g_deg[d], 1);
    }
}

// ---- multi-block scan: block sums -> tiny scan -> per-block rescan ----
__global__ void k_block_sums() {
    int i = blockIdx.x * SCAN_BLK + threadIdx.x;
    int v = (i < NN) ? g_deg[i] : 0;
    #pragma unroll
    for (int o = 16; o > 0; o >>= 1) v += __shfl_down_sync(0xffffffffu, v, o);
    __shared__ int ws[32];
    int wid = threadIdx.x >> 5, lane = threadIdx.x & 31;
    if (lane == 0) ws[wid] = v;
    __syncthreads();
    if (wid == 0) {
        int s = ws[lane];
        #pragma unroll
        for (int o = 16; o > 0; o >>= 1) s += __shfl_down_sync(0xffffffffu, s, o);
        if (lane == 0) g_part[blockIdx.x] = s;
    }
}

__global__ void k_scan_parts() {
    __shared__ int sm[128];
    int t = threadIdx.x;
    int v = (t < SCAN_NB) ? g_part[t] : 0;
    sm[t] = v;
    __syncthreads();
    #pragma unroll
    for (int o = 1; o < 128; o <<= 1) {
        int u = (t >= o) ? sm[t - o] : 0;
        __syncthreads();
        sm[t] += u;
        __syncthreads();
    }
    g_partoff[t] = sm[t] - v;   // exclusive
}

__global__ void k_scan_final() {
    int i = blockIdx.x * SCAN_BLK + threadIdx.x;
    int v = (i < NN) ? g_deg[i] : 0;
    int wid = threadIdx.x >> 5, lane = threadIdx.x & 31;
    // warp inclusive scan
    int incl = v;
    #pragma unroll
    for (int o = 1; o < 32; o <<= 1) {
        int u = __shfl_up_sync(0xffffffffu, incl, o);
        if (lane >= o) incl += u;
    }
    __shared__ int ws[32];
    if (lane == 31) ws[wid] = incl;
    __syncthreads();
    if (wid == 0) {
        int s = ws[lane];
        #pragma unroll
        for (int o = 1; o < 32; o <<= 1) {
            int u = __shfl_up_sync(0xffffffffu, s, o);
            if (lane >= o) s += u;
        }
        ws[lane] = s - ws[lane];   // exclusive warp base
    }
    __syncthreads();
    if (i < NN) {
        int e = incl - v + ws[wid] + g_partoff[blockIdx.x];
        g_off[i] = e;
        g_cur[i] = e;
    }
}

__global__ void k_fill(const void* __restrict__ ei) {
    int e = blockIdx.x * blockDim.x + threadIdx.x;
    if (e < EE) {
        int d = edge_at(ei, EE + e);
        int s = edge_at(ei, e);
        if ((unsigned)d < (unsigned)NN && (unsigned)s < (unsigned)NN) {
            int p = atomicAdd(&g_cur[d], 1);
            if ((unsigned)p < (unsigned)EE) g_csr[p] = s;
        }
    }
}

// ---------------- aggregation: h = (1+eps)*x + sum_{j in N(i)} x_j ----------------
template <int F, int SRC, int DST>
__global__ void k_agg(const float* __restrict__ xin,
                      const float* __restrict__ epsp) {
    int gw = (blockIdx.x * blockDim.x + threadIdx.x) >> 5;
    if (gw >= NN) return;
    int lane = threadIdx.x & 31;
    const float* src = (SRC < 0) ? xin : gbuf(SRC);
    float* h = gbuf(DST);
    float scale = 1.0f + __ldg(epsp);
    int start = g_off[gw];
    int end = g_cur[gw];
    if (start < 0) start = 0;
    if (end > EE) end = EE;
    if (end < start) end = start;

    if (F == 128) {
        const float4* x4 = (const float4*)src;
        float4 a = x4[gw * 32 + lane];
        float4 acc = make_float4(a.x * scale, a.y * scale, a.z * scale, a.w * scale);
        for (int j = start; j < end; j++) {
            int s = g_csr[j];
            float4 v = x4[s * 32 + lane];
            acc.x += v.x; acc.y += v.y; acc.z += v.z; acc.w += v.w;
        }
        ((float4*)h)[gw * 32 + lane] = acc;
    } else {
        const float2* x2 = (const float2*)src;
        float2 a = x2[gw * 32 + lane];
        float2 acc = make_float2(a.x * scale, a.y * scale);
        for (int j = start; j < end; j++) {
            int s = g_csr[j];
            float2 v = x2[s * 32 + lane];
            acc.x += v.x; acc.y += v.y;
        }
        ((float2*)h)[gw * 32 + lane] = acc;
    }
}

// ---------------- SGEMM: gbuf(DST) = relu(gbuf(SRC) @ W + b) ----------------
// BM=128, BN=HOUT (128 or 64), BK=16, 256 threads, TM=8 x TN=(BN/16) per thread
template <int K, int HOUT, bool RELU, int SRC, int DST>
__global__ __launch_bounds__(256) void k_gemm(const float* __restrict__ W,
                                              const float* __restrict__ B) {
    const int BM = 128, BN = HOUT, BK = 16;
    const int TM = 8, TN = BN / 16;          // 8 or 4
    __shared__ __align__(16) float As[BK][BM];
    __shared__ __align__(16) float Bs[BK][BN];

    const float* X = gbuf(SRC);
    float* Y = gbuf(DST);

    int tid = threadIdx.x;
    int row0 = blockIdx.x * BM;
    int tx = tid & 15;          // 0..15 -> TN cols each
    int ty = tid >> 4;          // 0..15 -> TM rows each

    float acc[TM][TN];
    #pragma unroll
    for (int i = 0; i < TM; i++)
        #pragma unroll
        for (int j = 0; j < TN; j++) acc[i][j] = 0.0f;

    for (int k0 = 0; k0 < K; k0 += BK) {
        // load A tile: BM x BK = 512 float4, 2 per thread; clamp row (safe, store guarded)
        #pragma unroll
        for (int l = 0; l < 2; l++) {
            int f = tid + l * 256;          // 0..511
            int r = f >> 2;                 // 0..127
            int kv = f & 3;                 // float4 within BK
            int arow = row0 + r;
            if (arow >= NN) arow = NN - 1;
            float4 av = *(const float4*)&X[arow * K + k0 + kv * 4];
            As[kv * 4 + 0][r] = av.x;
            As[kv * 4 + 1][r] = av.y;
            As[kv * 4 + 2][r] = av.z;
            As[kv * 4 + 3][r] = av.w;
        }
        // load B tile: BK x BN floats
        if (BN == 128) {
            #pragma unroll
            for (int l = 0; l < 2; l++) {
                int f = tid + l * 256;      // 0..511
                int rk = f >> 5;            // 0..15
                int c4 = f & 31;            // 0..31
                *(float4*)&Bs[rk][c4 * 4] = *(const float4*)&W[(k0 + rk) * HOUT + c4 * 4];
            }
        } else {                             // BN == 64: 256 float4
            int rk = tid >> 4;              // 0..15
            int c4 = tid & 15;              // 0..15
            *(float4*)&Bs[rk][c4 * 4] = *(const float4*)&W[(k0 + rk) * HOUT + c4 * 4];
        }
        __syncthreads();

        #pragma unroll
        for (int kk = 0; kk < BK; kk++) {
            float a[TM], b[TN];
            #pragma unroll
            for (int i = 0; i < TM; i += 4) {
                float4 a4 = *(float4*)&As[kk][ty * TM + i];
                a[i] = a4.x; a[i+1] = a4.y; a[i+2] = a4.z; a[i+3] = a4.w;
            }
            #pragma unroll
            for (int j = 0; j < TN; j += 4) {
                float4 b4 = *(float4*)&Bs[kk][tx * TN + j];
                b[j] = b4.x; b[j+1] = b4.y; b[j+2] = b4.z; b[j+3] = b4.w;
            }
            #pragma unroll
            for (int i = 0; i < TM; i++)
                #pragma unroll
                for (int j = 0; j < TN; j++)
                    acc[i][j] += a[i] * b[j];
        }
        __syncthreads();
    }

    // bias
    float bs[TN];
    #pragma unroll
    for (int j = 0; j < TN; j++) bs[j] = B[tx * TN + j];

    #pragma unroll
    for (int i = 0; i < TM; i++) {
        int r = row0 + ty * TM + i;
        if (r < NN) {
            #pragma unroll
            for (int j = 0; j < TN; j += 4) {
                float4 v;
                v.x = acc[i][j+0] + bs[j+0];
                v.y = acc[i][j+1] + bs[j+1];
                v.z = acc[i][j+2] + bs[j+2];
                v.w = acc[i][j+3] + bs[j+3];
                if (RELU) {
                    v.x = fmaxf(v.x, 0.f); v.y = fmaxf(v.y, 0.f);
                    v.z = fmaxf(v.z, 0.f); v.w = fmaxf(v.w, 0.f);
                }
                *(float4*)&Y[r * HOUT + tx * TN + j] = v;
            }
        }
    }
}

// ---------------- final FC (N,64)@(64,8)+b and emb copy ----------------
template <int SRC>
__global__ void k_fc(const float* __restrict__ W,
                     const float* __restrict__ B,
                     float* __restrict__ out,
                     float* __restrict__ emb) {
    int gw = (blockIdx.x * blockDim.x + threadIdx.x) >> 5;
    if (gw >= NN) return;
    int lane = threadIdx.x & 31;
    const float* X = gbuf(SRC);
    float v0 = X[gw * 64 + lane];
    float v1 = X[gw * 64 + 32 + lane];
    emb[gw * 64 + lane] = v0;
    emb[gw * 64 + 32 + lane] = v1;
    #pragma unroll
    for (int j = 0; j < 8; j++) {
        float p = v0 * W[lane * 8 + j] + v1 * W[(lane + 32) * 8 + j];
        #pragma unroll
        for (int o = 16; o > 0; o >>= 1)
            p += __shfl_down_sync(0xffffffffu, p, o);
        if (lane == 0) out[gw * 8 + j] = p + B[j];
    }
}

// ---------------- launch ----------------
extern "C" void kernel_launch(void* const* d_in, const int* in_sizes, int n_in,
                              void* d_out, int out_size) {
    const float* x    = (const float*)d_in[0];
    const void*  ei   = d_in[1];
    const float* eps1 = (const float*)d_in[2];
    const float* eps2 = (const float*)d_in[3];
    const float* eps3 = (const float*)d_in[4];
    const float* W1a  = (const float*)d_in[5];
    const float* b1a  = (const float*)d_in[6];
    const float* W1b  = (const float*)d_in[7];
    const float* b1b  = (const float*)d_in[8];
    const float* W2a  = (const float*)d_in[9];
    const float* b2a  = (const float*)d_in[10];
    const float* W2b  = (const float*)d_in[11];
    const float* b2b  = (const float*)d_in[12];
    const float* W3a  = (const float*)d_in[13];
    const float* b3a  = (const float*)d_in[14];
    const float* W3b  = (const float*)d_in[15];
    const float* b3b  = (const float*)d_in[16];
    const float* Wfc  = (const float*)d_in[17];
    const float* bfc  = (const float*)d_in[18];

    float* out = (float*)d_out;             // (N, 8)
    float* emb = out + NN * 8;              // (N, 64)

    // CSR build
    k_detect<<<1, 1024>>>((const long long*)ei);
    k_zero_deg<<<(NN + 255) / 256, 256>>>();
    k_hist<<<(EE + 255) / 256, 256>>>(ei);
    k_block_sums<<<SCAN_NB, SCAN_BLK>>>();
    k_scan_parts<<<1, 128>>>();
    k_scan_final<<<SCAN_NB, SCAN_BLK>>>();
    k_fill<<<(EE + 255) / 256, 256>>>(ei);

    const int aggBlocks = (NN * 32 + 255) / 256;
    const int gemmBlocks = (NN + 127) / 128;

    // Layer 1: F_IN=64 -> 128 -> 128
    k_agg<64, -1, 0><<<aggBlocks, 256>>>(x, eps1);
    k_gemm<64, 128, true, 0, 1><<<gemmBlocks, 256>>>(W1a, b1a);
    k_gemm<128, 128, true, 1, 2><<<gemmBlocks, 256>>>(W1b, b1b);

    // Layer 2: 128 -> 128 -> 128
    k_agg<128, 2, 0><<<aggBlocks, 256>>>(nullptr, eps2);
    k_gemm<128, 128, true, 0, 1><<<gemmBlocks, 256>>>(W2a, b2a);
    k_gemm<128, 128, true, 1, 2><<<gemmBlocks, 256>>>(W2b, b2b);

    // Layer 3: 128 -> 64 -> 64
    k_agg<128, 2, 0><<<aggBlocks, 256>>>(nullptr, eps3);
    k_gemm<128, 64, true, 0, 1><<<gemmBlocks, 256>>>(W3a, b3a);
    k_gemm<64, 64, true, 1, 2><<<gemmBlocks, 256>>>(W3b, b3b);

    // FC + emb
    k_fc<2><<<aggBlocks, 256>>>(Wfc, bfc, out, emb);
}

// round 8
// speedup vs baseline: 1.2809x; 1.0075x over previous
#include <cuda_runtime.h>

#define NN 100000
#define EE 1600000
#define SCAN_BLK 1024
#define SCAN_NB ((NN + SCAN_BLK - 1) / SCAN_BLK)   // 98

// ---------------- scratch (no allocations allowed) ----------------
__device__ int   g_is64;
__device__ int   g_deg[NN];
__device__ int   g_off[NN];
__device__ int   g_cur[NN];
__device__ int   g_csr[EE];
__device__ int   g_part[128];
__device__ int   g_partoff[128];
__device__ float g_h[NN * 128];
__device__ float g_t[NN * 128];
__device__ float g_x[NN * 128];

__device__ __forceinline__ float* gbuf(int i) {
    return (i == 0) ? g_h : (i == 1) ? g_t : g_x;
}

// ---------------- dtype detection (int64 vs silently-downcast int32) ----------------
__global__ void k_detect(const long long* __restrict__ e64) {
    __shared__ int bad;
    if (threadIdx.x == 0) bad = 0;
    __syncthreads();
    for (int i = threadIdx.x; i < 4096; i += blockDim.x) {
        long long v = e64[i];
        if (v < 0 || v >= NN) bad = 1;
    }
    __syncthreads();
    if (threadIdx.x == 0) g_is64 = bad ? 0 : 1;
}

// ---------------- CSR build ----------------
__global__ void k_zero_deg() {
    int i = blockIdx.x * blockDim.x + threadIdx.x;
    if (i < NN) g_deg[i] = 0;
}

__device__ __forceinline__ int edge_at(const void* ei, int idx) {
    if (g_is64) return (int)((const long long*)ei)[idx];
    return ((const int*)ei)[idx];
}

__global__ void k_hist(const void* __restrict__ ei) {
    int e = blockIdx.x * blockDim.x + threadIdx.x;
    if (e < EE) {
        int d = edge_at(ei, EE + e);
        if ((unsigned)d < (unsigned)NN) atomicAdd(&g_deg[d], 1);
    }
}

// ---- multi-block scan: block sums -> tiny scan -> per-block rescan ----
__global__ void k_block_sums() {
    int i = blockIdx.x * SCAN_BLK + threadIdx.x;
    int v = (i < NN) ? g_deg[i] : 0;
    #pragma unroll
    for (int o = 16; o > 0; o >>= 1) v += __shfl_down_sync(0xffffffffu, v, o);
    __shared__ int ws[32];
    int wid = threadIdx.x >> 5, lane = threadIdx.x & 31;
    if (lane == 0) ws[wid] = v;
    __syncthreads();
    if (wid == 0) {
        int s = ws[lane];
        #pragma unroll
        for (int o = 16; o > 0; o >>= 1) s += __shfl_down_sync(0xffffffffu, s, o);
        if (lane == 0) g_part[blockIdx.x] = s;
    }
}

__global__ void k_scan_parts() {
    __shared__ int sm[128];
    int t = threadIdx.x;
    int v = (t < SCAN_NB) ? g_part[t] : 0;
    sm[t] = v;
    __syncthreads();
    #pragma unroll
    for (int o = 1; o < 128; o <<= 1) {
        int u = (t >= o) ? sm[t - o] : 0;
        __syncthreads();
        sm[t] += u;
        __syncthreads();
    }
    g_partoff[t] = sm[t] - v;   // exclusive
}

__global__ void k_scan_final() {
    int i = blockIdx.x * SCAN_BLK + threadIdx.x;
    int v = (i < NN) ? g_deg[i] : 0;
    int wid = threadIdx.x >> 5, lane = threadIdx.x & 31;
    int incl = v;
    #pragma unroll
    for (int o = 1; o < 32; o <<= 1) {
        int u = __shfl_up_sync(0xffffffffu, incl, o);
        if (lane >= o) incl += u;
    }
    __shared__ int ws[32];
    if (lane == 31) ws[wid] = incl;
    __syncthreads();
    if (wid == 0) {
        int s = ws[lane];
        #pragma unroll
        for (int o = 1; o < 32; o <<= 1) {
            int u = __shfl_up_sync(0xffffffffu, s, o);
            if (lane >= o) s += u;
        }
        ws[lane] = s - ws[lane];   // exclusive warp base
    }
    __syncthreads();
    if (i < NN) {
        int e = incl - v + ws[wid] + g_partoff[blockIdx.x];
        g_off[i] = e;
        g_cur[i] = e;
    }
}

__global__ void k_fill(const void* __restrict__ ei) {
    int e = blockIdx.x * blockDim.x + threadIdx.x;
    if (e < EE) {
        int d = edge_at(ei, EE + e);
        int s = edge_at(ei, e);
        if ((unsigned)d < (unsigned)NN && (unsigned)s < (unsigned)NN) {
            int p = atomicAdd(&g_cur[d], 1);
            if ((unsigned)p < (unsigned)EE) g_csr[p] = s;
        }
    }
}

// ---------------- aggregation: h = (1+eps)*x + sum_{j in N(i)} x_j ----------------
template <int F, int SRC, int DST>
__global__ void k_agg(const float* __restrict__ xin,
                      const float* __restrict__ epsp) {
    int gw = (blockIdx.x * blockDim.x + threadIdx.x) >> 5;
    if (gw >= NN) return;
    int lane = threadIdx.x & 31;
    const float* src = (SRC < 0) ? xin : gbuf(SRC);
    float* h = gbuf(DST);
    float scale = 1.0f + __ldg(epsp);
    int start = g_off[gw];
    int end = g_cur[gw];
    if (start < 0) start = 0;
    if (end > EE) end = EE;
    if (end < start) end = start;

    if (F == 128) {
        const float4* x4 = (const float4*)src;
        float4 a = x4[gw * 32 + lane];
        float4 acc = make_float4(a.x * scale, a.y * scale, a.z * scale, a.w * scale);
        for (int j = start; j < end; j++) {
            int s = g_csr[j];
            float4 v = x4[s * 32 + lane];
            acc.x += v.x; acc.y += v.y; acc.z += v.z; acc.w += v.w;
        }
        ((float4*)h)[gw * 32 + lane] = acc;
    } else {
        const float2* x2 = (const float2*)src;
        float2 a = x2[gw * 32 + lane];
        float2 acc = make_float2(a.x * scale, a.y * scale);
        for (int j = start; j < end; j++) {
            int s = g_csr[j];
            float2 v = x2[s * 32 + lane];
            acc.x += v.x; acc.y += v.y;
        }
        ((float2*)h)[gw * 32 + lane] = acc;
    }
}

// ---------------- SGEMM via packed fma.rn.f32x2 (Blackwell 2x fp32 pipe) ----------------
// gbuf(DST) = relu(gbuf(SRC) @ W + b)
// BM=128, BN=HOUT (128 or 64), BK=16, 256 threads, TM=8 x TN=(BN/16) per thread.
// Accumulators are packed f32x2 pairs (bit-identical IEEE fp32 per half).
template <int K, int HOUT, bool RELU, int SRC, int DST>
__global__ __launch_bounds__(256) void k_gemm(const float* __restrict__ W,
                                              const float* __restrict__ B) {
    const int BM = 128, BN = HOUT, BK = 16;
    const int TM = 8, TN = BN / 16;          // 8 or 4
    const int TN2 = TN / 2;                  // 4 or 2
    __shared__ __align__(16) float As[BK][BM];
    __shared__ __align__(16) float Bs[BK][BN];

    const float* X = gbuf(SRC);
    float* Y = gbuf(DST);

    int tid = threadIdx.x;
    int row0 = blockIdx.x * BM;
    int tx = tid & 15;          // 0..15 -> TN cols each
    int ty = tid >> 4;          // 0..15 -> TM rows each

    unsigned long long acc2[TM][TN2];        // packed {f32,f32}; 0ull == {0.f,0.f}
    #pragma unroll
    for (int i = 0; i < TM; i++)
        #pragma unroll
        for (int j = 0; j < TN2; j++) acc2[i][j] = 0ull;

    for (int k0 = 0; k0 < K; k0 += BK) {
        // load A tile: BM x BK = 512 float4, 2 per thread; clamp row (safe, store guarded)
        #pragma unroll
        for (int l = 0; l < 2; l++) {
            int f = tid + l * 256;          // 0..511
            int r = f >> 2;                 // 0..127
            int kv = f & 3;                 // float4 within BK
            int arow = row0 + r;
            if (arow >= NN) arow = NN - 1;
            float4 av = *(const float4*)&X[arow * K + k0 + kv * 4];
            As[kv * 4 + 0][r] = av.x;
            As[kv * 4 + 1][r] = av.y;
            As[kv * 4 + 2][r] = av.z;
            As[kv * 4 + 3][r] = av.w;
        }
        // load B tile: BK x BN floats
        if (BN == 128) {
            #pragma unroll
            for (int l = 0; l < 2; l++) {
                int f = tid + l * 256;      // 0..511
                int rk = f >> 5;            // 0..15
                int c4 = f & 31;            // 0..31
                *(float4*)&Bs[rk][c4 * 4] = *(const float4*)&W[(k0 + rk) * HOUT + c4 * 4];
            }
        } else {                             // BN == 64: 256 float4
            int rk = tid >> 4;              // 0..15
            int c4 = tid & 15;              // 0..15
            *(float4*)&Bs[rk][c4 * 4] = *(const float4*)&W[(k0 + rk) * HOUT + c4 * 4];
        }
        __syncthreads();

        #pragma unroll
        for (int kk = 0; kk < BK; kk++) {
            // a scalars -> broadcast-packed {a,a}
            float a[TM];
            #pragma unroll
            for (int i = 0; i < TM; i += 4) {
                float4 a4 = *(float4*)&As[kk][ty * TM + i];
                a[i] = a4.x; a[i+1] = a4.y; a[i+2] = a4.z; a[i+3] = a4.w;
            }
            unsigned long long a2[TM];
            #pragma unroll
            for (int i = 0; i < TM; i++)
                asm("mov.b64 %0, {%1, %1};" : "=l"(a2[i]) : "f"(a[i]));
            // b pairs straight from shared as 64-bit values
            unsigned long long b2[TN2];
            const unsigned long long* bp =
                (const unsigned long long*)&Bs[kk][tx * TN];
            #pragma unroll
            for (int j = 0; j < TN2; j++) b2[j] = bp[j];
            // packed FMA: 2 fp32 FMAs per instruction
            #pragma unroll
            for (int i = 0; i < TM; i++)
                #pragma unroll
                for (int j = 0; j < TN2; j++)
                    asm("fma.rn.f32x2 %0, %1, %2, %0;"
                        : "+l"(acc2[i][j]) : "l"(a2[i]), "l"(b2[j]));
        }
        __syncthreads();
    }

    // unpack, bias, relu, store
    float bs[TN];
    #pragma unroll
    for (int j = 0; j < TN; j++) bs[j] = B[tx * TN + j];

    #pragma unroll
    for (int i = 0; i < TM; i++) {
        int r = row0 + ty * TM + i;
        if (r < NN) {
            float v[TN];
            #pragma unroll
            for (int j = 0; j < TN2; j++)
                asm("mov.b64 {%0, %1}, %2;"
                    : "=f"(v[2*j]), "=f"(v[2*j+1]) : "l"(acc2[i][j]));
            #pragma unroll
            for (int j = 0; j < TN; j += 4) {
                float4 o;
                o.x = v[j+0] + bs[j+0];
                o.y = v[j+1] + bs[j+1];
                o.z = v[j+2] + bs[j+2];
                o.w = v[j+3] + bs[j+3];
                if (RELU) {
                    o.x = fmaxf(o.x, 0.f); o.y = fmaxf(o.y, 0.f);
                    o.z = fmaxf(o.z, 0.f); o.w = fmaxf(o.w, 0.f);
                }
                *(float4*)&Y[r * HOUT + tx * TN + j] = o;
            }
        }
    }
}

// ---------------- final FC (N,64)@(64,8)+b and emb copy ----------------
template <int SRC>
__global__ void k_fc(const float* __restrict__ W,
                     const float* __restrict__ B,
                     float* __restrict__ out,
                     float* __restrict__ emb) {
    int gw = (blockIdx.x * blockDim.x + threadIdx.x) >> 5;
    if (gw >= NN) return;
    int lane = threadIdx.x & 31;
    const float* X = gbuf(SRC);
    float v0 = X[gw * 64 + lane];
    float v1 = X[gw * 64 + 32 + lane];
    emb[gw * 64 + lane] = v0;
    emb[gw * 64 + 32 + lane] = v1;
    #pragma unroll
    for (int j = 0; j < 8; j++) {
        float p = v0 * W[lane * 8 + j] + v1 * W[(lane + 32) * 8 + j];
        #pragma unroll
        for (int o = 16; o > 0; o >>= 1)
            p += __shfl_down_sync(0xffffffffu, p, o);
        if (lane == 0) out[gw * 8 + j] = p + B[j];
    }
}

// ---------------- launch ----------------
extern "C" void kernel_launch(void* const* d_in, const int* in_sizes, int n_in,
                              void* d_out, int out_size) {
    const float* x    = (const float*)d_in[0];
    const void*  ei   = d_in[1];
    const float* eps1 = (const float*)d_in[2];
    const float* eps2 = (const float*)d_in[3];
    const float* eps3 = (const float*)d_in[4];
    const float* W1a  = (const float*)d_in[5];
    const float* b1a  = (const float*)d_in[6];
    const float* W1b  = (const float*)d_in[7];
    const float* b1b  = (const float*)d_in[8];
    const float* W2a  = (const float*)d_in[9];
    const float* b2a  = (const float*)d_in[10];
    const float* W2b  = (const float*)d_in[11];
    const float* b2b  = (const float*)d_in[12];
    const float* W3a  = (const float*)d_in[13];
    const float* b3a  = (const float*)d_in[14];
    const float* W3b  = (const float*)d_in[15];
    const float* b3b  = (const float*)d_in[16];
    const float* Wfc  = (const float*)d_in[17];
    const float* bfc  = (const float*)d_in[18];

    float* out = (float*)d_out;             // (N, 8)
    float* emb = out + NN * 8;              // (N, 64)

    // CSR build
    k_detect<<<1, 1024>>>((const long long*)ei);
    k_zero_deg<<<(NN + 255) / 256, 256>>>();
    k_hist<<<(EE + 255) / 256, 256>>>(ei);
    k_block_sums<<<SCAN_NB, SCAN_BLK>>>();
    k_scan_parts<<<1, 128>>>();
    k_scan_final<<<SCAN_NB, SCAN_BLK>>>();
    k_fill<<<(EE + 255) / 256, 256>>>(ei);

    const int aggBlocks = (NN * 32 + 255) / 256;
    const int gemmBlocks = (NN + 127) / 128;

    // Layer 1: F_IN=64 -> 128 -> 128
    k_agg<64, -1, 0><<<aggBlocks, 256>>>(x, eps1);
    k_gemm<64, 128, true, 0, 1><<<gemmBlocks, 256>>>(W1a, b1a);
    k_gemm<128, 128, true, 1, 2><<<gemmBlocks, 256>>>(W1b, b1b);

    // Layer 2: 128 -> 128 -> 128
    k_agg<128, 2, 0><<<aggBlocks, 256>>>(nullptr, eps2);
    k_gemm<128, 128, true, 0, 1><<<gemmBlocks, 256>>>(W2a, b2a);
    k_gemm<128, 128, true, 1, 2><<<gemmBlocks, 256>>>(W2b, b2b);

    // Layer 3: 128 -> 64 -> 64
    k_agg<128, 2, 0><<<aggBlocks, 256>>>(nullptr, eps3);
    k_gemm<128, 64, true, 0, 1><<<gemmBlocks, 256>>>(W3a, b3a);
    k_gemm<64, 64, true, 1, 2><<<gemmBlocks, 256>>>(W3b, b3b);

    // FC + emb
    k_fc<2><<<aggBlocks, 256>>>(Wfc, bfc, out, emb);
}